// round 13
// baseline (speedup 1.0000x reference)
#include <cuda_runtime.h>
#include <cuda_fp16.h>
#include <math.h>
#include <cstdint>

static constexpr int Bc = 4;
static constexpr int Sc = 2048;
static constexpr int Ec = 1024;
static constexpr int Hc = 16;
static constexpr int Dc = 64;
static constexpr int Fc = 4096;
static constexpr int Mc = Bc * Sc;      // 8192 rows
static constexpr int E3 = 3 * Ec;       // 3072

// ---------------------------------------------------------------------------
// Scratch (device globals). Everything single fp16 except fp32 residual/out.
// ---------------------------------------------------------------------------
__device__ __half g_lnh [Mc * Ec];
__device__ __half g_qkvh[(size_t)Mc * E3];
__device__ __half g_ch  [Mc * Ec];
__device__ float  g_x2  [Mc * Ec];
__device__ __half g_hh  [(size_t)Mc * Fc];
__device__ __half g_wqkv[(size_t)E3 * Ec];
__device__ __half g_wo  [Ec * Ec];
__device__ __half g_w1  [(size_t)Fc * Ec];
__device__ __half g_w2  [(size_t)Ec * Fc];

// ---------------------------------------------------------------------------
// PTX helpers (plain sm_80+ features only; ptxas target is sm_103 non-'a')
// ---------------------------------------------------------------------------
__device__ __forceinline__ uint32_t smem_u32(const void* p) {
    uint32_t a;
    asm("{ .reg .u64 t; cvta.to.shared.u64 t, %1; cvt.u32.u64 %0, t; }" : "=r"(a) : "l"(p));
    return a;
}

#define CP16(dst, src) \
    asm volatile("cp.async.cg.shared.global [%0], [%1], 16;" :: "r"(dst), "l"(src))
#define CP_COMMIT() asm volatile("cp.async.commit_group;" ::: "memory")
#define CP_WAIT(n)  asm volatile("cp.async.wait_group %0;" :: "n"(n) : "memory")

__device__ __forceinline__ void ldsm_x4(uint32_t r[4], uint32_t addr) {
    asm volatile("ldmatrix.sync.aligned.m8n8.x4.shared.b16 {%0,%1,%2,%3}, [%4];"
        : "=r"(r[0]), "=r"(r[1]), "=r"(r[2]), "=r"(r[3]) : "r"(addr));
}
__device__ __forceinline__ void ldsm_x4_t(uint32_t r[4], uint32_t addr) {
    asm volatile("ldmatrix.sync.aligned.m8n8.x4.trans.shared.b16 {%0,%1,%2,%3}, [%4];"
        : "=r"(r[0]), "=r"(r[1]), "=r"(r[2]), "=r"(r[3]) : "r"(addr));
}
__device__ __forceinline__ void mma16816(float* c, const uint32_t* a,
                                         uint32_t b0, uint32_t b1) {
    asm volatile(
        "mma.sync.aligned.m16n8k16.row.col.f32.f16.f16.f32 "
        "{%0,%1,%2,%3}, {%4,%5,%6,%7}, {%8,%9}, {%0,%1,%2,%3};"
        : "+f"(c[0]), "+f"(c[1]), "+f"(c[2]), "+f"(c[3])
        : "r"(a[0]), "r"(a[1]), "r"(a[2]), "r"(a[3]), "r"(b0), "r"(b1));
}
// pack {even, odd} floats -> f16x2 (low half = even)
__device__ __forceinline__ uint32_t pack_f162(float even, float odd) {
    uint32_t r;
    asm("cvt.rn.f16x2.f32 %0, %1, %2;" : "=r"(r) : "f"(odd), "f"(even));
    return r;
}

// 128B-row swizzle (8 x 16B chunks per row)
#define SWZ(row, c) (((uint32_t)(row)) * 128u + ((((uint32_t)(c)) ^ ((uint32_t)(row) & 7u)) << 4))

__device__ __forceinline__ float gelu_exact(float x) {
    return 0.5f * x * (1.f + erff(x * 0.70710678118654752f));
}

// ---------------------------------------------------------------------------
// LayerNorm -> single fp16
// ---------------------------------------------------------------------------
__global__ __launch_bounds__(256) void ln_h_kernel(
    const float* __restrict__ x, const float* __restrict__ g,
    const float* __restrict__ b, __half* __restrict__ oh)
{
    __shared__ float red[8];
    const int row = blockIdx.x;
    const int t = threadIdx.x;
    const float* xr = x + (size_t)row * Ec;

    float v[4];
    float s = 0.f;
#pragma unroll
    for (int i = 0; i < 4; i++) { v[i] = xr[t + i * 256]; s += v[i]; }
#pragma unroll
    for (int m = 16; m; m >>= 1) s += __shfl_xor_sync(0xffffffffu, s, m);
    if ((t & 31) == 0) red[t >> 5] = s;
    __syncthreads();
    s = 0.f;
#pragma unroll
    for (int w = 0; w < 8; w++) s += red[w];
    const float mean = s * (1.f / Ec);
    __syncthreads();

    float sq = 0.f;
#pragma unroll
    for (int i = 0; i < 4; i++) { float d = v[i] - mean; sq += d * d; }
#pragma unroll
    for (int m = 16; m; m >>= 1) sq += __shfl_xor_sync(0xffffffffu, sq, m);
    if ((t & 31) == 0) red[t >> 5] = sq;
    __syncthreads();
    sq = 0.f;
#pragma unroll
    for (int w = 0; w < 8; w++) sq += red[w];
    const float rstd = rsqrtf(sq * (1.f / Ec) + 1e-5f);

#pragma unroll
    for (int i = 0; i < 4; i++) {
        int c = t + i * 256;
        float y = (v[i] - mean) * rstd * g[c] + b[c];
        oh[(size_t)row * Ec + c] = __float2half_rn(y);
    }
}

// ---------------------------------------------------------------------------
// fp32 -> fp16 weight converts, batched into 2 launches
// ---------------------------------------------------------------------------
__device__ __forceinline__ void conv4(const float* __restrict__ x,
                                      __half* __restrict__ h, int i)
{
    float4 v = ((const float4*)x)[i];
    __half2* hp = (__half2*)(h + 4 * (size_t)i);
    hp[0] = __halves2half2(__float2half_rn(v.x), __float2half_rn(v.y));
    hp[1] = __halves2half2(__float2half_rn(v.z), __float2half_rn(v.w));
}

__global__ __launch_bounds__(256) void conv_qkv_kernel(
    const float* __restrict__ Wq, const float* __restrict__ Wk,
    const float* __restrict__ Wv, __half* __restrict__ W)
{
    int bx = blockIdx.x;
    int mat = bx >> 10, li = (bx & 1023) * 256 + threadIdx.x;
    const float* src = (mat == 0) ? Wq : ((mat == 1) ? Wk : Wv);
    conv4(src, W + (size_t)mat * Ec * Ec, li);
}

__global__ __launch_bounds__(256) void conv_rest_kernel(
    const float* __restrict__ Wo, const float* __restrict__ W1,
    const float* __restrict__ W2, __half* __restrict__ wo,
    __half* __restrict__ w1, __half* __restrict__ w2)
{
    int bx = blockIdx.x;
    if (bx < 1024) {
        conv4(Wo, wo, bx * 256 + threadIdx.x);
    } else if (bx < 5120) {
        conv4(W1, w1, (bx - 1024) * 256 + threadIdx.x);
    } else {
        conv4(W2, w2, (bx - 5120) * 256 + threadIdx.x);
    }
}

// ---------------------------------------------------------------------------
// HMMA GEMM (NT), single fp16 x fp16, 64x64 warp tile, BK=64 chunks.
// CTA tile 128x128, 3 stages (prefetch distance 2), 128 threads,
// 4 warps (2m x 2n), 2 CTAs/SM. Stage 32KB: A 16K | B 16K.
// ---------------------------------------------------------------------------
static constexpr int GSTAGE = 32768;
static constexpr int NSTG = 3;
static constexpr int G_SMEM = NSTG * GSTAGE;   // 98304; x2 CTAs = 192KB

__device__ __forceinline__ uint32_t t_off64(int row, int c) {
    return ((uint32_t)row) * 128u + ((((uint32_t)c) ^ ((uint32_t)row & 7u)) << 4);
}

__device__ __forceinline__ void g_load2(
    const __half* __restrict__ A, const __half* __restrict__ B,
    int m0, int n0, int kk, int K, uint32_t sbase, int t)
{
#pragma unroll
    for (int i = 0; i < 8; i++) {
        int idx = t + i * 128;
        int row = idx >> 3, c = idx & 7;
        uint32_t off = t_off64(row, c);
        CP16(sbase + off, (const void*)(A + (size_t)(m0 + row) * K + kk + c * 8));
    }
#pragma unroll
    for (int i = 0; i < 8; i++) {
        int idx = t + i * 128;
        int row = idx >> 3, c = idx & 7;
        uint32_t off = t_off64(row, c);
        CP16(sbase + 16384 + off, (const void*)(B + (size_t)(n0 + row) * K + kk + c * 8));
    }
}

template <bool GELU, bool RES, bool OUTH, bool TRIPLE>
__global__ __launch_bounds__(128, 2) void gemm_mma(
    const __half* __restrict__ A, const __half* __restrict__ B,
    const float* __restrict__ bias, const float* __restrict__ bias2,
    const float* __restrict__ bias3, const float* __restrict__ res,
    float* __restrict__ C, __half* __restrict__ Ch, int N, int K)
{
    extern __shared__ char smem[];
    const uint32_t sb = smem_u32(smem);
    const int t = threadIdx.x;
    const int wid = t >> 5, lane = t & 31;
    const int wm = wid & 1, wn = wid >> 1;
    const int m0 = blockIdx.y * 128;
    const int n0 = blockIdx.x * 128;

    const int nk = K >> 6;     // 64-K chunks
    float acc[4][8][4] = {};

    const int a_row = wm * 64 + (lane & 15);
    const int b_row = wn * 64 + (lane & 7) + ((lane >> 4) & 1) * 8;
    const int a_ck  = (lane >> 4);
    const int b_ck  = ((lane >> 3) & 1);

#pragma unroll
    for (int s = 0; s < NSTG - 1; s++) {
        g_load2(A, B, m0, n0, s * 64, K, sb + s * GSTAGE, t);
        CP_COMMIT();
    }

    int stg_i = 0, pf_i = NSTG - 1;
    for (int c = 0; c < nk; c++) {
        CP_WAIT(NSTG - 2);
        __syncthreads();
        const int nx = c + NSTG - 1;
        if (nx < nk)
            g_load2(A, B, m0, n0, nx * 64, K, sb + pf_i * GSTAGE, t);
        CP_COMMIT();
        if (++pf_i == NSTG) pf_i = 0;

        const uint32_t stg = sb + stg_i * GSTAGE;
        if (++stg_i == NSTG) stg_i = 0;
        const uint32_t aH = stg, bH = stg + 16384;

#pragma unroll
        for (int p = 0; p < 4; p++) {
            const int ack = p * 2 + a_ck;
            const int bck = p * 2 + b_ck;

            uint32_t ah[4][4];
#pragma unroll
            for (int mi = 0; mi < 4; mi++)
                ldsm_x4(ah[mi], aH + t_off64(a_row + mi * 16, ack));

            uint32_t bh[8][2];
#pragma unroll
            for (int g = 0; g < 4; g++) {
                uint32_t r4[4];
                ldsm_x4(r4, bH + t_off64(b_row + g * 16, bck));
                bh[g * 2 + 0][0] = r4[0]; bh[g * 2 + 0][1] = r4[1];
                bh[g * 2 + 1][0] = r4[2]; bh[g * 2 + 1][1] = r4[3];
            }
#pragma unroll
            for (int mi = 0; mi < 4; mi++)
#pragma unroll
                for (int nj = 0; nj < 8; nj++)
                    mma16816(acc[mi][nj], ah[mi], bh[nj][0], bh[nj][1]);
        }
    }

    // epilogue
#pragma unroll
    for (int mi = 0; mi < 4; mi++) {
#pragma unroll
        for (int nj = 0; nj < 8; nj++) {
            const int r0  = m0 + wm * 64 + mi * 16 + (lane >> 2);
            const int col = n0 + wn * 64 + nj * 8 + 2 * (lane & 3);
            const float* bp = bias;
            int bcol = col;
            if (TRIPLE) {
                bp = (col >= 2048) ? bias3 : ((col >= 1024) ? bias2 : bias);
                bcol = col & 1023;
            }
            const float b0v = bp[bcol], b1v = bp[bcol + 1];
            float v00 = acc[mi][nj][0] + b0v, v01 = acc[mi][nj][1] + b1v;
            float v10 = acc[mi][nj][2] + b0v, v11 = acc[mi][nj][3] + b1v;
            if (GELU) {
                v00 = gelu_exact(v00); v01 = gelu_exact(v01);
                v10 = gelu_exact(v10); v11 = gelu_exact(v11);
            }
            if (OUTH) {
                *(__half2*)(Ch + (size_t)r0 * N + col) =
                    __halves2half2(__float2half_rn(v00), __float2half_rn(v01));
                *(__half2*)(Ch + (size_t)(r0 + 8) * N + col) =
                    __halves2half2(__float2half_rn(v10), __float2half_rn(v11));
            } else {
                if (RES) {
                    v00 += res[(size_t)r0 * N + col];
                    v01 += res[(size_t)r0 * N + col + 1];
                    v10 += res[(size_t)(r0 + 8) * N + col];
                    v11 += res[(size_t)(r0 + 8) * N + col + 1];
                }
                *(float2*)(C + (size_t)r0 * N + col)       = make_float2(v00, v01);
                *(float2*)(C + (size_t)(r0 + 8) * N + col) = make_float2(v10, v11);
            }
        }
    }
}

// ---------------------------------------------------------------------------
// Flash attention via HMMA, single fp16. 128-query tile, 8 warps (256 thr),
// warp w owns rows 16w..16w+15. K/V tiles 64 rows, double-buffered.
// SMEM: Q 16K | stage{0,1}: K 8K, V 8K  => 48KB; 4 CTAs/SM.
// ---------------------------------------------------------------------------
static constexpr int FA_SMEM = 49152;

__global__ __launch_bounds__(256) void flash_mma(
    const __half* __restrict__ qkv, __half* __restrict__ ctx)
{
    extern __shared__ char smem[];
    const uint32_t sb = smem_u32(smem);
    const int t = threadIdx.x, w = t >> 5, lane = t & 31;
    const int qt = (int)gridDim.x - 1 - (int)blockIdx.x;   // long pole first
    const int bh = blockIdx.y, bb = bh >> 4, hh = bh & 15;
    const int q0 = qt * 128;
    const size_t rowbase = (size_t)bb * Sc;
    const int colq = hh * 64, colk = 1024 + hh * 64, colv = 2048 + hh * 64;
    const int colE = hh * 64;

    // Q tile: 128 rows x 64 fp16 = 16KB
    for (int i = t; i < 1024; i += 256) {
        int r = i >> 3, c = i & 7;
        float4 val = *(const float4*)(qkv + (rowbase + q0 + r) * E3 + colq + c * 8);
        *(float4*)(smem + SWZ(r, c)) = val;
    }

    auto loadKV = [&](int kt, int stg) {
        uint32_t base = sb + 16384 + stg * 16384;
        for (int i = t; i < 1024; i += 256) {
            int which = i >> 9, j = i & 511;
            int r = j >> 3, c = j & 7;
            int colc = which ? colv : colk;
            CP16(base + which * 8192 + SWZ(r, c),
                 (const void*)(qkv + (rowbase + kt * 64 + r) * E3 + colc + c * 8));
        }
    };
    loadKV(0, 0); CP_COMMIT();

    float m_i[2] = {-INFINITY, -INFINITY}, l_i[2] = {0.f, 0.f};
    float o[8][4] = {};
    const int rl = lane >> 2;
    const int nkt = 2 * qt + 2;          // k-tiles covering causal span

    for (int kt = 0; kt < nkt; kt++) {
        if (kt + 1 < nkt) { loadKV(kt + 1, (kt + 1) & 1); CP_COMMIT(); CP_WAIT(1); }
        else              { CP_WAIT(0); }
        __syncthreads();
        const uint32_t stK = sb + 16384 + (kt & 1) * 16384;
        const uint32_t stV = stK + 8192;
        const int k0 = kt * 64;

        float sc[8][4] = {};
#pragma unroll
        for (int p = 0; p < 4; p++) {
            uint32_t af[4];
            int arow = w * 16 + (lane & 15);
            int ac = p * 2 + (lane >> 4);
            ldsm_x4(af, sb + SWZ(arow, ac));
#pragma unroll
            for (int g = 0; g < 4; g++) {
                uint32_t r4[4];
                int brow = g * 16 + (lane & 7) + ((lane >> 4) & 1) * 8;
                int bc = p * 2 + ((lane >> 3) & 1);
                ldsm_x4(r4, stK + SWZ(brow, bc));
                mma16816(sc[g * 2],     af, r4[0], r4[1]);
                mma16816(sc[g * 2 + 1], af, r4[2], r4[3]);
            }
        }
        const bool need_mask = (k0 + 63) > (q0 + w * 16);
#pragma unroll
        for (int nj = 0; nj < 8; nj++)
#pragma unroll
            for (int e = 0; e < 4; e++) {
                sc[nj][e] *= 0.125f;
                if (need_mask) {
                    int gcol = k0 + nj * 8 + 2 * (lane & 3) + (e & 1);
                    int grow = q0 + w * 16 + rl + ((e >= 2) ? 8 : 0);
                    if (gcol > grow) sc[nj][e] = -INFINITY;
                }
            }
        float mx0 = -INFINITY, mx1 = -INFINITY;
#pragma unroll
        for (int nj = 0; nj < 8; nj++) {
            mx0 = fmaxf(mx0, fmaxf(sc[nj][0], sc[nj][1]));
            mx1 = fmaxf(mx1, fmaxf(sc[nj][2], sc[nj][3]));
        }
        mx0 = fmaxf(mx0, __shfl_xor_sync(0xffffffffu, mx0, 1));
        mx0 = fmaxf(mx0, __shfl_xor_sync(0xffffffffu, mx0, 2));
        mx1 = fmaxf(mx1, __shfl_xor_sync(0xffffffffu, mx1, 1));
        mx1 = fmaxf(mx1, __shfl_xor_sync(0xffffffffu, mx1, 2));
        const float mn0 = fmaxf(m_i[0], mx0), mn1 = fmaxf(m_i[1], mx1);
        const float al0 = __expf(m_i[0] - mn0), al1 = __expf(m_i[1] - mn1);
        m_i[0] = mn0; m_i[1] = mn1;
        float rs0 = 0.f, rs1 = 0.f;
#pragma unroll
        for (int nj = 0; nj < 8; nj++) {
            sc[nj][0] = __expf(sc[nj][0] - mn0); rs0 += sc[nj][0];
            sc[nj][1] = __expf(sc[nj][1] - mn0); rs0 += sc[nj][1];
            sc[nj][2] = __expf(sc[nj][2] - mn1); rs1 += sc[nj][2];
            sc[nj][3] = __expf(sc[nj][3] - mn1); rs1 += sc[nj][3];
        }
        rs0 += __shfl_xor_sync(0xffffffffu, rs0, 1);
        rs0 += __shfl_xor_sync(0xffffffffu, rs0, 2);
        rs1 += __shfl_xor_sync(0xffffffffu, rs1, 1);
        rs1 += __shfl_xor_sync(0xffffffffu, rs1, 2);
        l_i[0] = l_i[0] * al0 + rs0;
        l_i[1] = l_i[1] * al1 + rs1;
#pragma unroll
        for (int dj = 0; dj < 8; dj++) {
            o[dj][0] *= al0; o[dj][1] *= al0;
            o[dj][2] *= al1; o[dj][3] *= al1;
        }
        uint32_t pa[4][4];
#pragma unroll
        for (int s = 0; s < 4; s++) {
            pa[s][0] = pack_f162(sc[2 * s][0], sc[2 * s][1]);
            pa[s][1] = pack_f162(sc[2 * s][2], sc[2 * s][3]);
            pa[s][2] = pack_f162(sc[2 * s + 1][0], sc[2 * s + 1][1]);
            pa[s][3] = pack_f162(sc[2 * s + 1][2], sc[2 * s + 1][3]);
        }
#pragma unroll
        for (int s = 0; s < 4; s++) {
#pragma unroll
            for (int g = 0; g < 4; g++) {
                uint32_t r4[4];
                int vrow = s * 16 + (lane & 7) + ((lane >> 3) & 1) * 8;
                int vc = g * 2 + (lane >> 4);
                ldsm_x4_t(r4, stV + SWZ(vrow, vc));
                mma16816(o[g * 2],     pa[s], r4[0], r4[1]);
                mma16816(o[g * 2 + 1], pa[s], r4[2], r4[3]);
            }
        }
        __syncthreads();
    }

    const float inv0 = 1.f / l_i[0], inv1 = 1.f / l_i[1];
#pragma unroll
    for (int dj = 0; dj < 8; dj++) {
        const int d = dj * 8 + 2 * (lane & 3);
        const size_t i0 = (rowbase + q0 + w * 16 + rl) * Ec + colE + d;
        const size_t i1 = i0 + 8 * Ec;
        *(__half2*)(ctx + i0) = __halves2half2(
            __float2half_rn(o[dj][0] * inv0), __float2half_rn(o[dj][1] * inv0));
        *(__half2*)(ctx + i1) = __halves2half2(
            __float2half_rn(o[dj][2] * inv1), __float2half_rn(o[dj][3] * inv1));
    }
}

// ---------------------------------------------------------------------------
// Launch. Order matters for ncu (-s 5 -c 1): launch #6 = O-projection GEMM.
// ---------------------------------------------------------------------------
extern "C" void kernel_launch(void* const* d_in, const int* in_sizes, int n_in,
                              void* d_out, int out_size)
{
    (void)in_sizes; (void)n_in; (void)out_size;
    const float* x     = (const float*)d_in[0];
    const float* ln1_g = (const float*)d_in[2];
    const float* ln1_b = (const float*)d_in[3];
    const float* Wq = (const float*)d_in[4];
    const float* bq = (const float*)d_in[5];
    const float* Wk = (const float*)d_in[6];
    const float* bk = (const float*)d_in[7];
    const float* Wv = (const float*)d_in[8];
    const float* bv = (const float*)d_in[9];
    const float* Wo = (const float*)d_in[10];
    const float* bo = (const float*)d_in[11];
    const float* ln2_g = (const float*)d_in[12];
    const float* ln2_b = (const float*)d_in[13];
    const float* W1 = (const float*)d_in[14];
    const float* b1 = (const float*)d_in[15];
    const float* W2 = (const float*)d_in[16];
    const float* b2 = (const float*)d_in[17];
    float* out = (float*)d_out;

    __half *lnh, *qkvh, *ch, *hh, *wqkv, *wo, *w1, *w2;
    float *x2;
    cudaGetSymbolAddress((void**)&lnh,  g_lnh);
    cudaGetSymbolAddress((void**)&qkvh, g_qkvh);
    cudaGetSymbolAddress((void**)&ch,   g_ch);
    cudaGetSymbolAddress((void**)&hh,   g_hh);
    cudaGetSymbolAddress((void**)&wqkv, g_wqkv);
    cudaGetSymbolAddress((void**)&wo,   g_wo);
    cudaGetSymbolAddress((void**)&w1,   g_w1);
    cudaGetSymbolAddress((void**)&w2,   g_w2);
    cudaGetSymbolAddress((void**)&x2,   g_x2);

    cudaFuncSetAttribute(gemm_mma<false, false, true,  true >, cudaFuncAttributeMaxDynamicSharedMemorySize, G_SMEM);
    cudaFuncSetAttribute(gemm_mma<false, true,  false, false>, cudaFuncAttributeMaxDynamicSharedMemorySize, G_SMEM);
    cudaFuncSetAttribute(gemm_mma<true,  false, true,  false>, cudaFuncAttributeMaxDynamicSharedMemorySize, G_SMEM);
    cudaFuncSetAttribute(flash_mma, cudaFuncAttributeMaxDynamicSharedMemorySize, FA_SMEM);

    // 1: LN1 -> fp16
    ln_h_kernel<<<Mc, 256>>>(x, ln1_g, ln1_b, lnh);
    // 2: Wq|Wk|Wv convert
    conv_qkv_kernel<<<3 * 1024, 256>>>(Wq, Wk, Wv, wqkv);
    // 3: Wo|W1|W2 convert
    conv_rest_kernel<<<9216, 256>>>(Wo, W1, W2, wo, w1, w2);
    // 4: fused QKV GEMM -> fp16 [M, 3E]
    gemm_mma<false, false, true, true><<<dim3(E3 / 128, Mc / 128), 128, G_SMEM>>>(
        lnh, wqkv, bq, bk, bv, nullptr, nullptr, qkvh, E3, Ec);
    // 5: attention -> fp16 ctx (128-query tiles)
    flash_mma<<<dim3(Sc / 128, Bc * Hc), 256, FA_SMEM>>>(qkvh, ch);
    // 6: O proj + residual(x) -> x2 (fp32)   <- ncu profiles this one
    gemm_mma<false, true, false, false><<<dim3(Ec / 128, Mc / 128), 128, G_SMEM>>>(
        ch, wo, bo, nullptr, nullptr, x, x2, nullptr, Ec, Ec);
    // 7: LN2 -> fp16
    ln_h_kernel<<<Mc, 256>>>(x2, ln2_g, ln2_b, lnh);
    // 8: FFN up + GELU -> fp16 hid
    gemm_mma<true, false, true, false><<<dim3(Fc / 128, Mc / 128), 128, G_SMEM>>>(
        lnh, w1, b1, nullptr, nullptr, nullptr, nullptr, hh, Fc, Ec);
    // 9: FFN down + residual(x2) -> out
    gemm_mma<false, true, false, false><<<dim3(Ec / 128, Mc / 128), 128, G_SMEM>>>(
        hh, w2, b2, nullptr, nullptr, x2, out, nullptr, Ec, Fc);
}

// round 14
// speedup vs baseline: 1.0648x; 1.0648x over previous
#include <cuda_runtime.h>
#include <cuda_fp16.h>
#include <math.h>
#include <cstdint>

static constexpr int Bc = 4;
static constexpr int Sc = 2048;
static constexpr int Ec = 1024;
static constexpr int Hc = 16;
static constexpr int Dc = 64;
static constexpr int Fc = 4096;
static constexpr int Mc = Bc * Sc;      // 8192 rows
static constexpr int E3 = 3 * Ec;       // 3072

// ---------------------------------------------------------------------------
// Scratch (device globals). Everything single fp16 except fp32 residual/out.
// ---------------------------------------------------------------------------
__device__ __half g_lnh [Mc * Ec];
__device__ __half g_qkvh[(size_t)Mc * E3];
__device__ __half g_ch  [Mc * Ec];
__device__ float  g_x2  [Mc * Ec];
__device__ __half g_hh  [(size_t)Mc * Fc];
__device__ __half g_wqkv[(size_t)E3 * Ec];
__device__ __half g_wo  [Ec * Ec];
__device__ __half g_w1  [(size_t)Fc * Ec];
__device__ __half g_w2  [(size_t)Ec * Fc];

// ---------------------------------------------------------------------------
// PTX helpers (plain sm_80+ features only; ptxas target is sm_103 non-'a')
// ---------------------------------------------------------------------------
__device__ __forceinline__ uint32_t smem_u32(const void* p) {
    uint32_t a;
    asm("{ .reg .u64 t; cvta.to.shared.u64 t, %1; cvt.u32.u64 %0, t; }" : "=r"(a) : "l"(p));
    return a;
}

#define CP16(dst, src) \
    asm volatile("cp.async.cg.shared.global [%0], [%1], 16;" :: "r"(dst), "l"(src))
#define CP_COMMIT() asm volatile("cp.async.commit_group;" ::: "memory")
#define CP_WAIT(n)  asm volatile("cp.async.wait_group %0;" :: "n"(n) : "memory")

__device__ __forceinline__ void ldsm_x4(uint32_t r[4], uint32_t addr) {
    asm volatile("ldmatrix.sync.aligned.m8n8.x4.shared.b16 {%0,%1,%2,%3}, [%4];"
        : "=r"(r[0]), "=r"(r[1]), "=r"(r[2]), "=r"(r[3]) : "r"(addr));
}
__device__ __forceinline__ void ldsm_x4_t(uint32_t r[4], uint32_t addr) {
    asm volatile("ldmatrix.sync.aligned.m8n8.x4.trans.shared.b16 {%0,%1,%2,%3}, [%4];"
        : "=r"(r[0]), "=r"(r[1]), "=r"(r[2]), "=r"(r[3]) : "r"(addr));
}
__device__ __forceinline__ void mma16816(float* c, const uint32_t* a,
                                         uint32_t b0, uint32_t b1) {
    asm volatile(
        "mma.sync.aligned.m16n8k16.row.col.f32.f16.f16.f32 "
        "{%0,%1,%2,%3}, {%4,%5,%6,%7}, {%8,%9}, {%0,%1,%2,%3};"
        : "+f"(c[0]), "+f"(c[1]), "+f"(c[2]), "+f"(c[3])
        : "r"(a[0]), "r"(a[1]), "r"(a[2]), "r"(a[3]), "r"(b0), "r"(b1));
}
// pack {even, odd} floats -> f16x2 (low half = even)
__device__ __forceinline__ uint32_t pack_f162(float even, float odd) {
    uint32_t r;
    asm("cvt.rn.f16x2.f32 %0, %1, %2;" : "=r"(r) : "f"(odd), "f"(even));
    return r;
}

// 128B-row swizzle (8 x 16B chunks per row)
#define SWZ(row, c) (((uint32_t)(row)) * 128u + ((((uint32_t)(c)) ^ ((uint32_t)(row) & 7u)) << 4))

__device__ __forceinline__ float gelu_exact(float x) {
    return 0.5f * x * (1.f + erff(x * 0.70710678118654752f));
}

// ---------------------------------------------------------------------------
// LayerNorm -> single fp16
// ---------------------------------------------------------------------------
__global__ __launch_bounds__(256) void ln_h_kernel(
    const float* __restrict__ x, const float* __restrict__ g,
    const float* __restrict__ b, __half* __restrict__ oh)
{
    __shared__ float red[8];
    const int row = blockIdx.x;
    const int t = threadIdx.x;
    const float* xr = x + (size_t)row * Ec;

    float v[4];
    float s = 0.f;
#pragma unroll
    for (int i = 0; i < 4; i++) { v[i] = xr[t + i * 256]; s += v[i]; }
#pragma unroll
    for (int m = 16; m; m >>= 1) s += __shfl_xor_sync(0xffffffffu, s, m);
    if ((t & 31) == 0) red[t >> 5] = s;
    __syncthreads();
    s = 0.f;
#pragma unroll
    for (int w = 0; w < 8; w++) s += red[w];
    const float mean = s * (1.f / Ec);
    __syncthreads();

    float sq = 0.f;
#pragma unroll
    for (int i = 0; i < 4; i++) { float d = v[i] - mean; sq += d * d; }
#pragma unroll
    for (int m = 16; m; m >>= 1) sq += __shfl_xor_sync(0xffffffffu, sq, m);
    if ((t & 31) == 0) red[t >> 5] = sq;
    __syncthreads();
    sq = 0.f;
#pragma unroll
    for (int w = 0; w < 8; w++) sq += red[w];
    const float rstd = rsqrtf(sq * (1.f / Ec) + 1e-5f);

#pragma unroll
    for (int i = 0; i < 4; i++) {
        int c = t + i * 256;
        float y = (v[i] - mean) * rstd * g[c] + b[c];
        oh[(size_t)row * Ec + c] = __float2half_rn(y);
    }
}

// ---------------------------------------------------------------------------
// fp32 -> fp16 weight converts, single launch for all 6 matrices
// grid = 3*1024 (qkv) + 1024 (wo) + 4096 (w1) + 4096 (w2) = 12288 blocks
// ---------------------------------------------------------------------------
__device__ __forceinline__ void conv4(const float* __restrict__ x,
                                      __half* __restrict__ h, int i)
{
    float4 v = ((const float4*)x)[i];
    __half2* hp = (__half2*)(h + 4 * (size_t)i);
    hp[0] = __halves2half2(__float2half_rn(v.x), __float2half_rn(v.y));
    hp[1] = __halves2half2(__float2half_rn(v.z), __float2half_rn(v.w));
}

__global__ __launch_bounds__(256) void conv_all_kernel(
    const float* __restrict__ Wq, const float* __restrict__ Wk,
    const float* __restrict__ Wv, const float* __restrict__ Wo,
    const float* __restrict__ W1, const float* __restrict__ W2,
    __half* __restrict__ wqkv, __half* __restrict__ wo,
    __half* __restrict__ w1, __half* __restrict__ w2)
{
    int bx = blockIdx.x;
    if (bx < 3072) {
        int mat = bx >> 10, li = (bx & 1023) * 256 + threadIdx.x;
        const float* src = (mat == 0) ? Wq : ((mat == 1) ? Wk : Wv);
        conv4(src, wqkv + (size_t)mat * Ec * Ec, li);
    } else if (bx < 4096) {
        conv4(Wo, wo, (bx - 3072) * 256 + threadIdx.x);
    } else if (bx < 8192) {
        conv4(W1, w1, (bx - 4096) * 256 + threadIdx.x);
    } else {
        conv4(W2, w2, (bx - 8192) * 256 + threadIdx.x);
    }
}

// ---------------------------------------------------------------------------
// HMMA GEMM (NT), single fp16 x fp16, 64x64 warp tile, BK=64 chunks.
// CTA tile 128x128, 3 stages (prefetch distance 2), 128 threads,
// 4 warps (2m x 2n), 2 CTAs/SM. Stage 32KB: A 16K | B 16K.
// ---------------------------------------------------------------------------
static constexpr int GSTAGE = 32768;
static constexpr int NSTG = 3;
static constexpr int G_SMEM = NSTG * GSTAGE;   // 98304; x2 CTAs = 192KB

__device__ __forceinline__ uint32_t t_off64(int row, int c) {
    return ((uint32_t)row) * 128u + ((((uint32_t)c) ^ ((uint32_t)row & 7u)) << 4);
}

__device__ __forceinline__ void g_load2(
    const __half* __restrict__ A, const __half* __restrict__ B,
    int m0, int n0, int kk, int K, uint32_t sbase, int t)
{
#pragma unroll
    for (int i = 0; i < 8; i++) {
        int idx = t + i * 128;
        int row = idx >> 3, c = idx & 7;
        uint32_t off = t_off64(row, c);
        CP16(sbase + off, (const void*)(A + (size_t)(m0 + row) * K + kk + c * 8));
    }
#pragma unroll
    for (int i = 0; i < 8; i++) {
        int idx = t + i * 128;
        int row = idx >> 3, c = idx & 7;
        uint32_t off = t_off64(row, c);
        CP16(sbase + 16384 + off, (const void*)(B + (size_t)(n0 + row) * K + kk + c * 8));
    }
}

template <bool GELU, bool RES, bool OUTH, bool TRIPLE>
__global__ __launch_bounds__(128, 2) void gemm_mma(
    const __half* __restrict__ A, const __half* __restrict__ B,
    const float* __restrict__ bias, const float* __restrict__ bias2,
    const float* __restrict__ bias3, const float* __restrict__ res,
    float* __restrict__ C, __half* __restrict__ Ch, int N, int K)
{
    extern __shared__ char smem[];
    const uint32_t sb = smem_u32(smem);
    const int t = threadIdx.x;
    const int wid = t >> 5, lane = t & 31;
    const int wm = wid & 1, wn = wid >> 1;
    const int m0 = blockIdx.y * 128;
    const int n0 = blockIdx.x * 128;

    const int nk = K >> 6;     // 64-K chunks
    float acc[4][8][4] = {};

    const int a_row = wm * 64 + (lane & 15);
    const int b_row = wn * 64 + (lane & 7) + ((lane >> 4) & 1) * 8;
    const int a_ck  = (lane >> 4);
    const int b_ck  = ((lane >> 3) & 1);

#pragma unroll
    for (int s = 0; s < NSTG - 1; s++) {
        g_load2(A, B, m0, n0, s * 64, K, sb + s * GSTAGE, t);
        CP_COMMIT();
    }

    int stg_i = 0, pf_i = NSTG - 1;
    for (int c = 0; c < nk; c++) {
        CP_WAIT(NSTG - 2);
        __syncthreads();
        const int nx = c + NSTG - 1;
        if (nx < nk)
            g_load2(A, B, m0, n0, nx * 64, K, sb + pf_i * GSTAGE, t);
        CP_COMMIT();
        if (++pf_i == NSTG) pf_i = 0;

        const uint32_t stg = sb + stg_i * GSTAGE;
        if (++stg_i == NSTG) stg_i = 0;
        const uint32_t aH = stg, bH = stg + 16384;

#pragma unroll
        for (int p = 0; p < 4; p++) {
            const int ack = p * 2 + a_ck;
            const int bck = p * 2 + b_ck;

            uint32_t ah[4][4];
#pragma unroll
            for (int mi = 0; mi < 4; mi++)
                ldsm_x4(ah[mi], aH + t_off64(a_row + mi * 16, ack));

            uint32_t bh[8][2];
#pragma unroll
            for (int g = 0; g < 4; g++) {
                uint32_t r4[4];
                ldsm_x4(r4, bH + t_off64(b_row + g * 16, bck));
                bh[g * 2 + 0][0] = r4[0]; bh[g * 2 + 0][1] = r4[1];
                bh[g * 2 + 1][0] = r4[2]; bh[g * 2 + 1][1] = r4[3];
            }
#pragma unroll
            for (int mi = 0; mi < 4; mi++)
#pragma unroll
                for (int nj = 0; nj < 8; nj++)
                    mma16816(acc[mi][nj], ah[mi], bh[nj][0], bh[nj][1]);
        }
    }

    // epilogue
#pragma unroll
    for (int mi = 0; mi < 4; mi++) {
#pragma unroll
        for (int nj = 0; nj < 8; nj++) {
            const int r0  = m0 + wm * 64 + mi * 16 + (lane >> 2);
            const int col = n0 + wn * 64 + nj * 8 + 2 * (lane & 3);
            const float* bp = bias;
            int bcol = col;
            if (TRIPLE) {
                bp = (col >= 2048) ? bias3 : ((col >= 1024) ? bias2 : bias);
                bcol = col & 1023;
            }
            const float b0v = bp[bcol], b1v = bp[bcol + 1];
            float v00 = acc[mi][nj][0] + b0v, v01 = acc[mi][nj][1] + b1v;
            float v10 = acc[mi][nj][2] + b0v, v11 = acc[mi][nj][3] + b1v;
            if (GELU) {
                v00 = gelu_exact(v00); v01 = gelu_exact(v01);
                v10 = gelu_exact(v10); v11 = gelu_exact(v11);
            }
            if (OUTH) {
                *(__half2*)(Ch + (size_t)r0 * N + col) =
                    __halves2half2(__float2half_rn(v00), __float2half_rn(v01));
                *(__half2*)(Ch + (size_t)(r0 + 8) * N + col) =
                    __halves2half2(__float2half_rn(v10), __float2half_rn(v11));
            } else {
                if (RES) {
                    v00 += res[(size_t)r0 * N + col];
                    v01 += res[(size_t)r0 * N + col + 1];
                    v10 += res[(size_t)(r0 + 8) * N + col];
                    v11 += res[(size_t)(r0 + 8) * N + col + 1];
                }
                *(float2*)(C + (size_t)r0 * N + col)       = make_float2(v00, v01);
                *(float2*)(C + (size_t)(r0 + 8) * N + col) = make_float2(v10, v11);
            }
        }
    }
}

// ---------------------------------------------------------------------------
// Flash attention via HMMA, single fp16 operands. 64-query tile, 4 warps.
// q/k/v from fused [M, 3E] fp16 buffer (stride 3072).
// 3-stage K/V pipeline (prefetch distance 2) -> single sync per k-tile.
// SMEM: Q 8K | stage{0,1,2}: K 8K, V 8K  => 56KB
// ---------------------------------------------------------------------------
static constexpr int FA_SMEM = 57344;

__global__ __launch_bounds__(128) void flash_mma(
    const __half* __restrict__ qkv, __half* __restrict__ ctx)
{
    extern __shared__ char smem[];
    const uint32_t sb = smem_u32(smem);
    const int t = threadIdx.x, w = t >> 5, lane = t & 31;
    const int qt = (int)gridDim.x - 1 - (int)blockIdx.x;   // long pole first
    const int bh = blockIdx.y, bb = bh >> 4, hh = bh & 15;
    const int q0 = qt * 64;
    const size_t rowbase = (size_t)bb * Sc;
    const int colq = hh * 64, colk = 1024 + hh * 64, colv = 2048 + hh * 64;
    const int colE = hh * 64;

    for (int i = t; i < 512; i += 128) {
        int r = i >> 3, c = i & 7;
        float4 val = *(const float4*)(qkv + (rowbase + q0 + r) * E3 + colq + c * 8);
        *(float4*)(smem + SWZ(r, c)) = val;
    }

    auto loadKV = [&](int kt, int stg) {
        uint32_t base = sb + 8192 + stg * 16384;
        for (int i = t; i < 1024; i += 128) {
            int which = i >> 9, j = i & 511;
            int r = j >> 3, c = j & 7;
            int colc = which ? colv : colk;
            CP16(base + which * 8192 + SWZ(r, c),
                 (const void*)(qkv + (rowbase + kt * 64 + r) * E3 + colc + c * 8));
        }
    };
    // prologue: two tiles in flight (commit both groups unconditionally)
    loadKV(0, 0); CP_COMMIT();
    if (qt >= 1) loadKV(1, 1);
    CP_COMMIT();

    float m_i[2] = {-INFINITY, -INFINITY}, l_i[2] = {0.f, 0.f};
    float o[8][4] = {};
    const int rl = lane >> 2;

    int stg_i = 0, pf_i = 2;
    for (int kt = 0; kt <= qt; kt++) {
        CP_WAIT(1);
        __syncthreads();
        const int nx = kt + 2;
        if (nx <= qt) loadKV(nx, pf_i);
        CP_COMMIT();
        if (++pf_i == 3) pf_i = 0;

        const uint32_t stK = sb + 8192 + stg_i * 16384;
        const uint32_t stV = stK + 8192;
        if (++stg_i == 3) stg_i = 0;

        float sc[8][4] = {};
#pragma unroll
        for (int p = 0; p < 4; p++) {
            uint32_t af[4];
            int arow = w * 16 + (lane & 15);
            int ac = p * 2 + (lane >> 4);
            ldsm_x4(af, sb + SWZ(arow, ac));
#pragma unroll
            for (int g = 0; g < 4; g++) {
                uint32_t r4[4];
                int brow = g * 16 + (lane & 7) + ((lane >> 4) & 1) * 8;
                int bc = p * 2 + ((lane >> 3) & 1);
                ldsm_x4(r4, stK + SWZ(brow, bc));
                mma16816(sc[g * 2],     af, r4[0], r4[1]);
                mma16816(sc[g * 2 + 1], af, r4[2], r4[3]);
            }
        }
#pragma unroll
        for (int nj = 0; nj < 8; nj++)
#pragma unroll
            for (int e = 0; e < 4; e++) {
                sc[nj][e] *= 0.125f;
                if (kt == qt) {
                    int col = nj * 8 + 2 * (lane & 3) + (e & 1);
                    int row = w * 16 + rl + ((e >= 2) ? 8 : 0);
                    if (col > row) sc[nj][e] = -INFINITY;
                }
            }
        float mx0 = -INFINITY, mx1 = -INFINITY;
#pragma unroll
        for (int nj = 0; nj < 8; nj++) {
            mx0 = fmaxf(mx0, fmaxf(sc[nj][0], sc[nj][1]));
            mx1 = fmaxf(mx1, fmaxf(sc[nj][2], sc[nj][3]));
        }
        mx0 = fmaxf(mx0, __shfl_xor_sync(0xffffffffu, mx0, 1));
        mx0 = fmaxf(mx0, __shfl_xor_sync(0xffffffffu, mx0, 2));
        mx1 = fmaxf(mx1, __shfl_xor_sync(0xffffffffu, mx1, 1));
        mx1 = fmaxf(mx1, __shfl_xor_sync(0xffffffffu, mx1, 2));
        const float mn0 = fmaxf(m_i[0], mx0), mn1 = fmaxf(m_i[1], mx1);
        const float al0 = __expf(m_i[0] - mn0), al1 = __expf(m_i[1] - mn1);
        m_i[0] = mn0; m_i[1] = mn1;
        float rs0 = 0.f, rs1 = 0.f;
#pragma unroll
        for (int nj = 0; nj < 8; nj++) {
            sc[nj][0] = __expf(sc[nj][0] - mn0); rs0 += sc[nj][0];
            sc[nj][1] = __expf(sc[nj][1] - mn0); rs0 += sc[nj][1];
            sc[nj][2] = __expf(sc[nj][2] - mn1); rs1 += sc[nj][2];
            sc[nj][3] = __expf(sc[nj][3] - mn1); rs1 += sc[nj][3];
        }
        rs0 += __shfl_xor_sync(0xffffffffu, rs0, 1);
        rs0 += __shfl_xor_sync(0xffffffffu, rs0, 2);
        rs1 += __shfl_xor_sync(0xffffffffu, rs1, 1);
        rs1 += __shfl_xor_sync(0xffffffffu, rs1, 2);
        l_i[0] = l_i[0] * al0 + rs0;
        l_i[1] = l_i[1] * al1 + rs1;
#pragma unroll
        for (int dj = 0; dj < 8; dj++) {
            o[dj][0] *= al0; o[dj][1] *= al0;
            o[dj][2] *= al1; o[dj][3] *= al1;
        }
        uint32_t pa[4][4];
#pragma unroll
        for (int s = 0; s < 4; s++) {
            pa[s][0] = pack_f162(sc[2 * s][0], sc[2 * s][1]);
            pa[s][1] = pack_f162(sc[2 * s][2], sc[2 * s][3]);
            pa[s][2] = pack_f162(sc[2 * s + 1][0], sc[2 * s + 1][1]);
            pa[s][3] = pack_f162(sc[2 * s + 1][2], sc[2 * s + 1][3]);
        }
#pragma unroll
        for (int s = 0; s < 4; s++) {
#pragma unroll
            for (int g = 0; g < 4; g++) {
                uint32_t r4[4];
                int vrow = s * 16 + (lane & 7) + ((lane >> 3) & 1) * 8;
                int vc = g * 2 + (lane >> 4);
                ldsm_x4_t(r4, stV + SWZ(vrow, vc));
                mma16816(o[g * 2],     pa[s], r4[0], r4[1]);
                mma16816(o[g * 2 + 1], pa[s], r4[2], r4[3]);
            }
        }
    }

    const float inv0 = 1.f / l_i[0], inv1 = 1.f / l_i[1];
#pragma unroll
    for (int dj = 0; dj < 8; dj++) {
        const int d = dj * 8 + 2 * (lane & 3);
        const size_t i0 = (rowbase + q0 + w * 16 + rl) * Ec + colE + d;
        const size_t i1 = i0 + 8 * Ec;
        *(__half2*)(ctx + i0) = __halves2half2(
            __float2half_rn(o[dj][0] * inv0), __float2half_rn(o[dj][1] * inv0));
        *(__half2*)(ctx + i1) = __halves2half2(
            __float2half_rn(o[dj][2] * inv1), __float2half_rn(o[dj][3] * inv1));
    }
}

// ---------------------------------------------------------------------------
// Launch. Order matters for ncu (-s 5 -c 1): launch #5 = O-projection GEMM.
// ---------------------------------------------------------------------------
extern "C" void kernel_launch(void* const* d_in, const int* in_sizes, int n_in,
                              void* d_out, int out_size)
{
    (void)in_sizes; (void)n_in; (void)out_size;
    const float* x     = (const float*)d_in[0];
    const float* ln1_g = (const float*)d_in[2];
    const float* ln1_b = (const float*)d_in[3];
    const float* Wq = (const float*)d_in[4];
    const float* bq = (const float*)d_in[5];
    const float* Wk = (const float*)d_in[6];
    const float* bk = (const float*)d_in[7];
    const float* Wv = (const float*)d_in[8];
    const float* bv = (const float*)d_in[9];
    const float* Wo = (const float*)d_in[10];
    const float* bo = (const float*)d_in[11];
    const float* ln2_g = (const float*)d_in[12];
    const float* ln2_b = (const float*)d_in[13];
    const float* W1 = (const float*)d_in[14];
    const float* b1 = (const float*)d_in[15];
    const float* W2 = (const float*)d_in[16];
    const float* b2 = (const float*)d_in[17];
    float* out = (float*)d_out;

    __half *lnh, *qkvh, *ch, *hh, *wqkv, *wo, *w1, *w2;
    float *x2;
    cudaGetSymbolAddress((void**)&lnh,  g_lnh);
    cudaGetSymbolAddress((void**)&qkvh, g_qkvh);
    cudaGetSymbolAddress((void**)&ch,   g_ch);
    cudaGetSymbolAddress((void**)&hh,   g_hh);
    cudaGetSymbolAddress((void**)&wqkv, g_wqkv);
    cudaGetSymbolAddress((void**)&wo,   g_wo);
    cudaGetSymbolAddress((void**)&w1,   g_w1);
    cudaGetSymbolAddress((void**)&w2,   g_w2);
    cudaGetSymbolAddress((void**)&x2,   g_x2);

    cudaFuncSetAttribute(gemm_mma<false, false, true,  true >, cudaFuncAttributeMaxDynamicSharedMemorySize, G_SMEM);
    cudaFuncSetAttribute(gemm_mma<false, true,  false, false>, cudaFuncAttributeMaxDynamicSharedMemorySize, G_SMEM);
    cudaFuncSetAttribute(gemm_mma<true,  false, true,  false>, cudaFuncAttributeMaxDynamicSharedMemorySize, G_SMEM);
    cudaFuncSetAttribute(flash_mma, cudaFuncAttributeMaxDynamicSharedMemorySize, FA_SMEM);

    // 1: LN1 -> fp16
    ln_h_kernel<<<Mc, 256>>>(x, ln1_g, ln1_b, lnh);
    // 2: all weight converts in one launch
    conv_all_kernel<<<12288, 256>>>(Wq, Wk, Wv, Wo, W1, W2, wqkv, wo, w1, w2);
    // 3: fused QKV GEMM -> fp16 [M, 3E]
    gemm_mma<false, false, true, true><<<dim3(E3 / 128, Mc / 128), 128, G_SMEM>>>(
        lnh, wqkv, bq, bk, bv, nullptr, nullptr, qkvh, E3, Ec);
    // 4: attention -> fp16 ctx
    flash_mma<<<dim3(Sc / 64, Bc * Hc), 128, FA_SMEM>>>(qkvh, ch);
    // 5: O proj + residual(x) -> x2 (fp32)
    gemm_mma<false, true, false, false><<<dim3(Ec / 128, Mc / 128), 128, G_SMEM>>>(
        ch, wo, bo, nullptr, nullptr, x, x2, nullptr, Ec, Ec);
    // 6: LN2 -> fp16   <- ncu (-s 5) profiles this one; fine, GEMMs are known
    ln_h_kernel<<<Mc, 256>>>(x2, ln2_g, ln2_b, lnh);
    // 7: FFN up + GELU -> fp16 hid
    gemm_mma<true, false, true, false><<<dim3(Fc / 128, Mc / 128), 128, G_SMEM>>>(
        lnh, w1, b1, nullptr, nullptr, nullptr, nullptr, hh, Fc, Ec);
    // 8: FFN down + residual(x2) -> out
    gemm_mma<false, true, false, false><<<dim3(Ec / 128, Mc / 128), 128, G_SMEM>>>(
        hh, w2, b2, nullptr, nullptr, x2, out, nullptr, Ec, Fc);
}

// round 15
// speedup vs baseline: 1.0765x; 1.0109x over previous
#include <cuda_runtime.h>
#include <cuda_fp16.h>
#include <math.h>
#include <cstdint>

static constexpr int Bc = 4;
static constexpr int Sc = 2048;
static constexpr int Ec = 1024;
static constexpr int Hc = 16;
static constexpr int Dc = 64;
static constexpr int Fc = 4096;
static constexpr int Mc = Bc * Sc;      // 8192 rows
static constexpr int E3 = 3 * Ec;       // 3072

// ---------------------------------------------------------------------------
// Scratch (device globals). Everything single fp16 except fp32 residual/out.
// ---------------------------------------------------------------------------
__device__ __half g_lnh [Mc * Ec];
__device__ __half g_qkvh[(size_t)Mc * E3];
__device__ __half g_ch  [Mc * Ec];
__device__ float  g_x2  [Mc * Ec];
__device__ __half g_hh  [(size_t)Mc * Fc];
__device__ __half g_wqkv[(size_t)E3 * Ec];
__device__ __half g_wo  [Ec * Ec];
__device__ __half g_w1  [(size_t)Fc * Ec];
__device__ __half g_w2  [(size_t)Ec * Fc];

// ---------------------------------------------------------------------------
// PTX helpers (plain sm_80+ features only; ptxas target is sm_103 non-'a')
// ---------------------------------------------------------------------------
__device__ __forceinline__ uint32_t smem_u32(const void* p) {
    uint32_t a;
    asm("{ .reg .u64 t; cvta.to.shared.u64 t, %1; cvt.u32.u64 %0, t; }" : "=r"(a) : "l"(p));
    return a;
}

#define CP16(dst, src) \
    asm volatile("cp.async.cg.shared.global [%0], [%1], 16;" :: "r"(dst), "l"(src))
#define CP_COMMIT() asm volatile("cp.async.commit_group;" ::: "memory")
#define CP_WAIT(n)  asm volatile("cp.async.wait_group %0;" :: "n"(n) : "memory")

__device__ __forceinline__ void ldsm_x4(uint32_t r[4], uint32_t addr) {
    asm volatile("ldmatrix.sync.aligned.m8n8.x4.shared.b16 {%0,%1,%2,%3}, [%4];"
        : "=r"(r[0]), "=r"(r[1]), "=r"(r[2]), "=r"(r[3]) : "r"(addr));
}
__device__ __forceinline__ void ldsm_x4_t(uint32_t r[4], uint32_t addr) {
    asm volatile("ldmatrix.sync.aligned.m8n8.x4.trans.shared.b16 {%0,%1,%2,%3}, [%4];"
        : "=r"(r[0]), "=r"(r[1]), "=r"(r[2]), "=r"(r[3]) : "r"(addr));
}
__device__ __forceinline__ void mma16816(float* c, const uint32_t* a,
                                         uint32_t b0, uint32_t b1) {
    asm volatile(
        "mma.sync.aligned.m16n8k16.row.col.f32.f16.f16.f32 "
        "{%0,%1,%2,%3}, {%4,%5,%6,%7}, {%8,%9}, {%0,%1,%2,%3};"
        : "+f"(c[0]), "+f"(c[1]), "+f"(c[2]), "+f"(c[3])
        : "r"(a[0]), "r"(a[1]), "r"(a[2]), "r"(a[3]), "r"(b0), "r"(b1));
}
// pack {even, odd} floats -> f16x2 (low half = even)
__device__ __forceinline__ uint32_t pack_f162(float even, float odd) {
    uint32_t r;
    asm("cvt.rn.f16x2.f32 %0, %1, %2;" : "=r"(r) : "f"(odd), "f"(even));
    return r;
}

// 128B-row swizzle (8 x 16B chunks per row)
#define SWZ(row, c) (((uint32_t)(row)) * 128u + ((((uint32_t)(c)) ^ ((uint32_t)(row) & 7u)) << 4))

__device__ __forceinline__ float gelu_exact(float x) {
    return 0.5f * x * (1.f + erff(x * 0.70710678118654752f));
}

// ---------------------------------------------------------------------------
// LayerNorm -> single fp16
// ---------------------------------------------------------------------------
__global__ __launch_bounds__(256) void ln_h_kernel(
    const float* __restrict__ x, const float* __restrict__ g,
    const float* __restrict__ b, __half* __restrict__ oh)
{
    __shared__ float red[8];
    const int row = blockIdx.x;
    const int t = threadIdx.x;
    const float* xr = x + (size_t)row * Ec;

    float v[4];
    float s = 0.f;
#pragma unroll
    for (int i = 0; i < 4; i++) { v[i] = xr[t + i * 256]; s += v[i]; }
#pragma unroll
    for (int m = 16; m; m >>= 1) s += __shfl_xor_sync(0xffffffffu, s, m);
    if ((t & 31) == 0) red[t >> 5] = s;
    __syncthreads();
    s = 0.f;
#pragma unroll
    for (int w = 0; w < 8; w++) s += red[w];
    const float mean = s * (1.f / Ec);
    __syncthreads();

    float sq = 0.f;
#pragma unroll
    for (int i = 0; i < 4; i++) { float d = v[i] - mean; sq += d * d; }
#pragma unroll
    for (int m = 16; m; m >>= 1) sq += __shfl_xor_sync(0xffffffffu, sq, m);
    if ((t & 31) == 0) red[t >> 5] = sq;
    __syncthreads();
    sq = 0.f;
#pragma unroll
    for (int w = 0; w < 8; w++) sq += red[w];
    const float rstd = rsqrtf(sq * (1.f / Ec) + 1e-5f);

#pragma unroll
    for (int i = 0; i < 4; i++) {
        int c = t + i * 256;
        float y = (v[i] - mean) * rstd * g[c] + b[c];
        oh[(size_t)row * Ec + c] = __float2half_rn(y);
    }
}

// ---------------------------------------------------------------------------
// fp32 -> fp16 weight converts, single launch for all 6 matrices
// ---------------------------------------------------------------------------
__device__ __forceinline__ void conv4(const float* __restrict__ x,
                                      __half* __restrict__ h, int i)
{
    float4 v = ((const float4*)x)[i];
    __half2* hp = (__half2*)(h + 4 * (size_t)i);
    hp[0] = __halves2half2(__float2half_rn(v.x), __float2half_rn(v.y));
    hp[1] = __halves2half2(__float2half_rn(v.z), __float2half_rn(v.w));
}

__global__ __launch_bounds__(256) void conv_all_kernel(
    const float* __restrict__ Wq, const float* __restrict__ Wk,
    const float* __restrict__ Wv, const float* __restrict__ Wo,
    const float* __restrict__ W1, const float* __restrict__ W2,
    __half* __restrict__ wqkv, __half* __restrict__ wo,
    __half* __restrict__ w1, __half* __restrict__ w2)
{
    int bx = blockIdx.x;
    if (bx < 3072) {
        int mat = bx >> 10, li = (bx & 1023) * 256 + threadIdx.x;
        const float* src = (mat == 0) ? Wq : ((mat == 1) ? Wk : Wv);
        conv4(src, wqkv + (size_t)mat * Ec * Ec, li);
    } else if (bx < 4096) {
        conv4(Wo, wo, (bx - 3072) * 256 + threadIdx.x);
    } else if (bx < 8192) {
        conv4(W1, w1, (bx - 4096) * 256 + threadIdx.x);
    } else {
        conv4(W2, w2, (bx - 8192) * 256 + threadIdx.x);
    }
}

// ---------------------------------------------------------------------------
// HMMA GEMM (NT), single fp16 x fp16, 64x64 warp tile, BK=64 chunks.
// CTA tile 128x128, 3 stages (prefetch distance 2), 128 threads,
// 4 warps (2m x 2n), 2 CTAs/SM. Stage 32KB: A 16K | B 16K.
// ---------------------------------------------------------------------------
static constexpr int GSTAGE = 32768;
static constexpr int NSTG = 3;
static constexpr int G_SMEM = NSTG * GSTAGE;   // 98304; x2 CTAs = 192KB

__device__ __forceinline__ uint32_t t_off64(int row, int c) {
    return ((uint32_t)row) * 128u + ((((uint32_t)c) ^ ((uint32_t)row & 7u)) << 4);
}

__device__ __forceinline__ void g_load2(
    const __half* __restrict__ A, const __half* __restrict__ B,
    int m0, int n0, int kk, int K, uint32_t sbase, int t)
{
#pragma unroll
    for (int i = 0; i < 8; i++) {
        int idx = t + i * 128;
        int row = idx >> 3, c = idx & 7;
        uint32_t off = t_off64(row, c);
        CP16(sbase + off, (const void*)(A + (size_t)(m0 + row) * K + kk + c * 8));
    }
#pragma unroll
    for (int i = 0; i < 8; i++) {
        int idx = t + i * 128;
        int row = idx >> 3, c = idx & 7;
        uint32_t off = t_off64(row, c);
        CP16(sbase + 16384 + off, (const void*)(B + (size_t)(n0 + row) * K + kk + c * 8));
    }
}

template <bool GELU, bool RES, bool OUTH, bool TRIPLE>
__global__ __launch_bounds__(128, 2) void gemm_mma(
    const __half* __restrict__ A, const __half* __restrict__ B,
    const float* __restrict__ bias, const float* __restrict__ bias2,
    const float* __restrict__ bias3, const float* __restrict__ res,
    float* __restrict__ C, __half* __restrict__ Ch, int N, int K)
{
    extern __shared__ char smem[];
    const uint32_t sb = smem_u32(smem);
    const int t = threadIdx.x;
    const int wid = t >> 5, lane = t & 31;
    const int wm = wid & 1, wn = wid >> 1;
    const int m0 = blockIdx.y * 128;
    const int n0 = blockIdx.x * 128;

    const int nk = K >> 6;     // 64-K chunks
    float acc[4][8][4] = {};

    const int a_row = wm * 64 + (lane & 15);
    const int b_row = wn * 64 + (lane & 7) + ((lane >> 4) & 1) * 8;
    const int a_ck  = (lane >> 4);
    const int b_ck  = ((lane >> 3) & 1);

#pragma unroll
    for (int s = 0; s < NSTG - 1; s++) {
        g_load2(A, B, m0, n0, s * 64, K, sb + s * GSTAGE, t);
        CP_COMMIT();
    }

    int stg_i = 0, pf_i = NSTG - 1;
    for (int c = 0; c < nk; c++) {
        CP_WAIT(NSTG - 2);
        __syncthreads();
        const int nx = c + NSTG - 1;
        if (nx < nk)
            g_load2(A, B, m0, n0, nx * 64, K, sb + pf_i * GSTAGE, t);
        CP_COMMIT();
        if (++pf_i == NSTG) pf_i = 0;

        const uint32_t stg = sb + stg_i * GSTAGE;
        if (++stg_i == NSTG) stg_i = 0;
        const uint32_t aH = stg, bH = stg + 16384;

#pragma unroll
        for (int p = 0; p < 4; p++) {
            const int ack = p * 2 + a_ck;
            const int bck = p * 2 + b_ck;

            uint32_t ah[4][4];
#pragma unroll
            for (int mi = 0; mi < 4; mi++)
                ldsm_x4(ah[mi], aH + t_off64(a_row + mi * 16, ack));

            uint32_t bh[8][2];
#pragma unroll
            for (int g = 0; g < 4; g++) {
                uint32_t r4[4];
                ldsm_x4(r4, bH + t_off64(b_row + g * 16, bck));
                bh[g * 2 + 0][0] = r4[0]; bh[g * 2 + 0][1] = r4[1];
                bh[g * 2 + 1][0] = r4[2]; bh[g * 2 + 1][1] = r4[3];
            }
#pragma unroll
            for (int mi = 0; mi < 4; mi++)
#pragma unroll
                for (int nj = 0; nj < 8; nj++)
                    mma16816(acc[mi][nj], ah[mi], bh[nj][0], bh[nj][1]);
        }
    }

    // epilogue
#pragma unroll
    for (int mi = 0; mi < 4; mi++) {
#pragma unroll
        for (int nj = 0; nj < 8; nj++) {
            const int r0  = m0 + wm * 64 + mi * 16 + (lane >> 2);
            const int col = n0 + wn * 64 + nj * 8 + 2 * (lane & 3);
            const float* bp = bias;
            int bcol = col;
            if (TRIPLE) {
                bp = (col >= 2048) ? bias3 : ((col >= 1024) ? bias2 : bias);
                bcol = col & 1023;
            }
            const float b0v = bp[bcol], b1v = bp[bcol + 1];
            float v00 = acc[mi][nj][0] + b0v, v01 = acc[mi][nj][1] + b1v;
            float v10 = acc[mi][nj][2] + b0v, v11 = acc[mi][nj][3] + b1v;
            if (GELU) {
                v00 = gelu_exact(v00); v01 = gelu_exact(v01);
                v10 = gelu_exact(v10); v11 = gelu_exact(v11);
            }
            if (OUTH) {
                *(__half2*)(Ch + (size_t)r0 * N + col) =
                    __halves2half2(__float2half_rn(v00), __float2half_rn(v01));
                *(__half2*)(Ch + (size_t)(r0 + 8) * N + col) =
                    __halves2half2(__float2half_rn(v10), __float2half_rn(v11));
            } else {
                if (RES) {
                    v00 += res[(size_t)r0 * N + col];
                    v01 += res[(size_t)r0 * N + col + 1];
                    v10 += res[(size_t)(r0 + 8) * N + col];
                    v11 += res[(size_t)(r0 + 8) * N + col + 1];
                }
                *(float2*)(C + (size_t)r0 * N + col)       = make_float2(v00, v01);
                *(float2*)(C + (size_t)(r0 + 8) * N + col) = make_float2(v10, v11);
            }
        }
    }
}

// ---------------------------------------------------------------------------
// Flash attention via HMMA, single fp16. 64-query tile, 4 warps.
// Q fragments preloaded in registers; exp2-folded softmax (scale in exponent).
// 3-stage K/V pipeline. SMEM: Q 8K | stage{0,1,2}: K 8K, V 8K => 56KB
// ---------------------------------------------------------------------------
static constexpr int FA_SMEM = 57344;
static constexpr float EXC = 0.18033688011112042f;   // 0.125 * log2(e)

__global__ __launch_bounds__(128) void flash_mma(
    const __half* __restrict__ qkv, __half* __restrict__ ctx)
{
    extern __shared__ char smem[];
    const uint32_t sb = smem_u32(smem);
    const int t = threadIdx.x, w = t >> 5, lane = t & 31;
    const int qt = (int)gridDim.x - 1 - (int)blockIdx.x;   // long pole first
    const int bh = blockIdx.y, bb = bh >> 4, hh = bh & 15;
    const int q0 = qt * 64;
    const size_t rowbase = (size_t)bb * Sc;
    const int colq = hh * 64, colk = 1024 + hh * 64, colv = 2048 + hh * 64;
    const int colE = hh * 64;

    for (int i = t; i < 512; i += 128) {
        int r = i >> 3, c = i & 7;
        float4 val = *(const float4*)(qkv + (rowbase + q0 + r) * E3 + colq + c * 8);
        *(float4*)(smem + SWZ(r, c)) = val;
    }

    auto loadKV = [&](int kt, int stg) {
        uint32_t base = sb + 8192 + stg * 16384;
        for (int i = t; i < 1024; i += 128) {
            int which = i >> 9, j = i & 511;
            int r = j >> 3, c = j & 7;
            int colc = which ? colv : colk;
            CP16(base + which * 8192 + SWZ(r, c),
                 (const void*)(qkv + (rowbase + kt * 64 + r) * E3 + colc + c * 8));
        }
    };
    loadKV(0, 0); CP_COMMIT();
    if (qt >= 1) loadKV(1, 1);
    CP_COMMIT();

    // Preload Q fragments (invariant over the whole kt loop)
    __syncthreads();
    uint32_t qf[4][4];
    {
        const int arow = w * 16 + (lane & 15);
#pragma unroll
        for (int p = 0; p < 4; p++)
            ldsm_x4(qf[p], sb + SWZ(arow, p * 2 + (lane >> 4)));
    }

    float m_i[2] = {-INFINITY, -INFINITY}, l_i[2] = {0.f, 0.f};
    float o[8][4] = {};
    const int rl = lane >> 2;

    int stg_i = 0, pf_i = 2;
    for (int kt = 0; kt <= qt; kt++) {
        CP_WAIT(1);
        __syncthreads();
        const int nx = kt + 2;
        if (nx <= qt) loadKV(nx, pf_i);
        CP_COMMIT();
        if (++pf_i == 3) pf_i = 0;

        const uint32_t stK = sb + 8192 + stg_i * 16384;
        const uint32_t stV = stK + 8192;
        if (++stg_i == 3) stg_i = 0;

        float sc[8][4] = {};
#pragma unroll
        for (int p = 0; p < 4; p++) {
#pragma unroll
            for (int g = 0; g < 4; g++) {
                uint32_t r4[4];
                int brow = g * 16 + (lane & 7) + ((lane >> 4) & 1) * 8;
                int bc = p * 2 + ((lane >> 3) & 1);
                ldsm_x4(r4, stK + SWZ(brow, bc));
                mma16816(sc[g * 2],     qf[p], r4[0], r4[1]);
                mma16816(sc[g * 2 + 1], qf[p], r4[2], r4[3]);
            }
        }
        // causal mask on diagonal tile (raw scores; scale folded into exp)
        if (kt == qt) {
#pragma unroll
            for (int nj = 0; nj < 8; nj++)
#pragma unroll
                for (int e = 0; e < 4; e++) {
                    int col = nj * 8 + 2 * (lane & 3) + (e & 1);
                    int row = w * 16 + rl + ((e >= 2) ? 8 : 0);
                    if (col > row) sc[nj][e] = -INFINITY;
                }
        }
        float mx0 = -INFINITY, mx1 = -INFINITY;
#pragma unroll
        for (int nj = 0; nj < 8; nj++) {
            mx0 = fmaxf(mx0, fmaxf(sc[nj][0], sc[nj][1]));
            mx1 = fmaxf(mx1, fmaxf(sc[nj][2], sc[nj][3]));
        }
        mx0 = fmaxf(mx0, __shfl_xor_sync(0xffffffffu, mx0, 1));
        mx0 = fmaxf(mx0, __shfl_xor_sync(0xffffffffu, mx0, 2));
        mx1 = fmaxf(mx1, __shfl_xor_sync(0xffffffffu, mx1, 1));
        mx1 = fmaxf(mx1, __shfl_xor_sync(0xffffffffu, mx1, 2));
        const float mn0 = fmaxf(m_i[0], mx0), mn1 = fmaxf(m_i[1], mx1);
        const float al0 = exp2f((m_i[0] - mn0) * EXC);
        const float al1 = exp2f((m_i[1] - mn1) * EXC);
        m_i[0] = mn0; m_i[1] = mn1;
        const float mc0 = mn0 * EXC, mc1 = mn1 * EXC;
        float rs0 = 0.f, rs1 = 0.f;
#pragma unroll
        for (int nj = 0; nj < 8; nj++) {
            sc[nj][0] = exp2f(fmaf(sc[nj][0], EXC, -mc0)); rs0 += sc[nj][0];
            sc[nj][1] = exp2f(fmaf(sc[nj][1], EXC, -mc0)); rs0 += sc[nj][1];
            sc[nj][2] = exp2f(fmaf(sc[nj][2], EXC, -mc1)); rs1 += sc[nj][2];
            sc[nj][3] = exp2f(fmaf(sc[nj][3], EXC, -mc1)); rs1 += sc[nj][3];
        }
        rs0 += __shfl_xor_sync(0xffffffffu, rs0, 1);
        rs0 += __shfl_xor_sync(0xffffffffu, rs0, 2);
        rs1 += __shfl_xor_sync(0xffffffffu, rs1, 1);
        rs1 += __shfl_xor_sync(0xffffffffu, rs1, 2);
        l_i[0] = l_i[0] * al0 + rs0;
        l_i[1] = l_i[1] * al1 + rs1;
#pragma unroll
        for (int dj = 0; dj < 8; dj++) {
            o[dj][0] *= al0; o[dj][1] *= al0;
            o[dj][2] *= al1; o[dj][3] *= al1;
        }
        uint32_t pa[4][4];
#pragma unroll
        for (int s = 0; s < 4; s++) {
            pa[s][0] = pack_f162(sc[2 * s][0], sc[2 * s][1]);
            pa[s][1] = pack_f162(sc[2 * s][2], sc[2 * s][3]);
            pa[s][2] = pack_f162(sc[2 * s + 1][0], sc[2 * s + 1][1]);
            pa[s][3] = pack_f162(sc[2 * s + 1][2], sc[2 * s + 1][3]);
        }
#pragma unroll
        for (int s = 0; s < 4; s++) {
#pragma unroll
            for (int g = 0; g < 4; g++) {
                uint32_t r4[4];
                int vrow = s * 16 + (lane & 7) + ((lane >> 3) & 1) * 8;
                int vc = g * 2 + (lane >> 4);
                ldsm_x4_t(r4, stV + SWZ(vrow, vc));
                mma16816(o[g * 2],     pa[s], r4[0], r4[1]);
                mma16816(o[g * 2 + 1], pa[s], r4[2], r4[3]);
            }
        }
    }

    const float inv0 = 1.f / l_i[0], inv1 = 1.f / l_i[1];
#pragma unroll
    for (int dj = 0; dj < 8; dj++) {
        const int d = dj * 8 + 2 * (lane & 3);
        const size_t i0 = (rowbase + q0 + w * 16 + rl) * Ec + colE + d;
        const size_t i1 = i0 + 8 * Ec;
        *(__half2*)(ctx + i0) = __halves2half2(
            __float2half_rn(o[dj][0] * inv0), __float2half_rn(o[dj][1] * inv0));
        *(__half2*)(ctx + i1) = __halves2half2(
            __float2half_rn(o[dj][2] * inv1), __float2half_rn(o[dj][3] * inv1));
    }
}

// ---------------------------------------------------------------------------
// Launch
// ---------------------------------------------------------------------------
extern "C" void kernel_launch(void* const* d_in, const int* in_sizes, int n_in,
                              void* d_out, int out_size)
{
    (void)in_sizes; (void)n_in; (void)out_size;
    const float* x     = (const float*)d_in[0];
    const float* ln1_g = (const float*)d_in[2];
    const float* ln1_b = (const float*)d_in[3];
    const float* Wq = (const float*)d_in[4];
    const float* bq = (const float*)d_in[5];
    const float* Wk = (const float*)d_in[6];
    const float* bk = (const float*)d_in[7];
    const float* Wv = (const float*)d_in[8];
    const float* bv = (const float*)d_in[9];
    const float* Wo = (const float*)d_in[10];
    const float* bo = (const float*)d_in[11];
    const float* ln2_g = (const float*)d_in[12];
    const float* ln2_b = (const float*)d_in[13];
    const float* W1 = (const float*)d_in[14];
    const float* b1 = (const float*)d_in[15];
    const float* W2 = (const float*)d_in[16];
    const float* b2 = (const float*)d_in[17];
    float* out = (float*)d_out;

    __half *lnh, *qkvh, *ch, *hh, *wqkv, *wo, *w1, *w2;
    float *x2;
    cudaGetSymbolAddress((void**)&lnh,  g_lnh);
    cudaGetSymbolAddress((void**)&qkvh, g_qkvh);
    cudaGetSymbolAddress((void**)&ch,   g_ch);
    cudaGetSymbolAddress((void**)&hh,   g_hh);
    cudaGetSymbolAddress((void**)&wqkv, g_wqkv);
    cudaGetSymbolAddress((void**)&wo,   g_wo);
    cudaGetSymbolAddress((void**)&w1,   g_w1);
    cudaGetSymbolAddress((void**)&w2,   g_w2);
    cudaGetSymbolAddress((void**)&x2,   g_x2);

    cudaFuncSetAttribute(gemm_mma<false, false, true,  true >, cudaFuncAttributeMaxDynamicSharedMemorySize, G_SMEM);
    cudaFuncSetAttribute(gemm_mma<false, true,  false, false>, cudaFuncAttributeMaxDynamicSharedMemorySize, G_SMEM);
    cudaFuncSetAttribute(gemm_mma<true,  false, true,  false>, cudaFuncAttributeMaxDynamicSharedMemorySize, G_SMEM);
    cudaFuncSetAttribute(flash_mma, cudaFuncAttributeMaxDynamicSharedMemorySize, FA_SMEM);

    // 1: LN1 -> fp16
    ln_h_kernel<<<Mc, 256>>>(x, ln1_g, ln1_b, lnh);
    // 2: all weight converts in one launch
    conv_all_kernel<<<12288, 256>>>(Wq, Wk, Wv, Wo, W1, W2, wqkv, wo, w1, w2);
    // 3: fused QKV GEMM -> fp16 [M, 3E]
    gemm_mma<false, false, true, true><<<dim3(E3 / 128, Mc / 128), 128, G_SMEM>>>(
        lnh, wqkv, bq, bk, bv, nullptr, nullptr, qkvh, E3, Ec);
    // 4: attention -> fp16 ctx
    flash_mma<<<dim3(Sc / 64, Bc * Hc), 128, FA_SMEM>>>(qkvh, ch);
    // 5: O proj + residual(x) -> x2 (fp32)
    gemm_mma<false, true, false, false><<<dim3(Ec / 128, Mc / 128), 128, G_SMEM>>>(
        ch, wo, bo, nullptr, nullptr, x, x2, nullptr, Ec, Ec);
    // 6: LN2 -> fp16
    ln_h_kernel<<<Mc, 256>>>(x2, ln2_g, ln2_b, lnh);
    // 7: FFN up + GELU -> fp16 hid
    gemm_mma<true, false, true, false><<<dim3(Fc / 128, Mc / 128), 128, G_SMEM>>>(
        lnh, w1, b1, nullptr, nullptr, nullptr, nullptr, hh, Fc, Ec);
    // 8: FFN down + residual(x2) -> out
    gemm_mma<false, true, false, false><<<dim3(Ec / 128, Mc / 128), 128, G_SMEM>>>(
        hh, w2, b2, nullptr, nullptr, x2, out, nullptr, Ec, Fc);
}